// round 2
// baseline (speedup 1.0000x reference)
#include <cuda_runtime.h>

// Fixed shapes: x = (4,64,256,256) f32, stoken = 16
#define Bn 4
#define Cc 64
#define NH 16      // superpixel grid 16x16
#define NS 256     // nH*nW
#define PP 65536   // H*W

// Scratch (allocation-free: __device__ globals)
__device__ float g_cent[Bn * NS * Cc];
__device__ float g_num [Bn * NS * Cc];
__device__ float g_den [Bn * NS];
__device__ float g_aff [Bn * 9 * PP];     // compact affinities, [b][k][p]

// ---------------------------------------------------------------------------
// Initial centroids: block mean over each 16x16 block. Also zeroes scratch.
// ---------------------------------------------------------------------------
__global__ __launch_bounds__(256) void init_cent_kernel(const float* __restrict__ x) {
    int b = blockIdx.y, s = blockIdx.x;
    int bi = s >> 4, bj = s & 15;
    int tid = threadIdx.x;
    int c = tid >> 2, g = tid & 3;
    const float* fc = x + (((size_t)b * Cc + c) << 16);
    int base = ((bi * 16) << 8) + bj * 16;
    float acc = 0.f;
    #pragma unroll 8
    for (int i = g; i < 256; i += 4)
        acc += fc[base + ((i >> 4) << 8) + (i & 15)];
    __shared__ float part[256];
    part[tid] = acc;
    __syncthreads();
    if (tid < 64) {
        int o4 = tid * 4;
        float v = part[o4] + part[o4 + 1] + part[o4 + 2] + part[o4 + 3];
        int idx = (b * NS + s) * Cc + tid;
        g_cent[idx] = v * (1.f / 256.f);
        g_num[idx]  = 0.f;
    }
    if (tid == 64) g_den[b * NS + s] = 0.f;
}

// ---------------------------------------------------------------------------
// Affinity pass. One CTA per (b, 16x16 pixel block); 256 threads = 256 pixels.
// PASS 0: centroids from g_cent; fused num/den reduction with global atomics.
// PASS 1: centroids from g_num/g_den (fused finalize); writes compact g_aff.
// ---------------------------------------------------------------------------
template <int PASS>
__global__ __launch_bounds__(256) void affinity_kernel(const float* __restrict__ x) {
    int b = blockIdx.y, sblk = blockIdx.x;
    int bi = sblk >> 4, bj = sblk & 15;
    int tid = threadIdx.x;

    __shared__ float cent_sm[9][64];
    __shared__ float c2_sm[9];
    __shared__ float den_sm[9];
    __shared__ int   cand_s[9];
    __shared__ int   cand_v[9];

    if (tid < 9) {
        int ci = bi + tid / 3 - 1, cj = bj + tid % 3 - 1;
        int v = (ci >= 0 && ci < NH && cj >= 0 && cj < NH);
        cand_v[tid] = v;
        int s = v ? ci * NH + cj : 0;
        cand_s[tid] = s;
        if (PASS == 1) den_sm[tid] = g_den[b * NS + s] + 1e-16f;
    }
    __syncthreads();
    for (int i = tid; i < 9 * 64; i += 256) {
        int k = i >> 6, c = i & 63;
        int gi = (b * NS + cand_s[k]) * Cc + c;
        cent_sm[k][c] = (PASS == 0) ? g_cent[gi] : g_num[gi] / den_sm[k];
    }
    __syncthreads();
    if (tid < 9) {
        float s2 = 0.f;
        #pragma unroll 8
        for (int c = 0; c < 64; c++) { float v = cent_sm[tid][c]; s2 += v * v; }
        c2_sm[tid] = s2;
    }
    __syncthreads();

    // ---- per-pixel dots over 64 channels against 9 staged centroids ----
    int ly = tid >> 4, lx = tid & 15;
    int p = ((bi * 16 + ly) << 8) + bj * 16 + lx;
    const float* fb = x + (((size_t)b * Cc) << 16) + p;
    float f2 = 0.f;
    float dot[9];
    #pragma unroll
    for (int k = 0; k < 9; k++) dot[k] = 0.f;
    #pragma unroll 4
    for (int c = 0; c < 64; c++) {
        float f = fb[(size_t)c << 16];
        f2 = fmaf(f, f, f2);
        #pragma unroll
        for (int k = 0; k < 9; k++) dot[k] = fmaf(f, cent_sm[k][c], dot[k]);
    }

    // ---- masked softmax over 9 candidates ----
    float aff[9];
    float mx = -3.0e38f;
    #pragma unroll
    for (int k = 0; k < 9; k++) {
        float d = f2 + c2_sm[k] - 2.f * dot[k];
        aff[k] = cand_v[k] ? -d : -1e30f;
        mx = fmaxf(mx, aff[k]);
    }
    float ssum = 0.f;
    #pragma unroll
    for (int k = 0; k < 9; k++) { float e = __expf(aff[k] - mx); aff[k] = e; ssum += e; }
    float rs = 1.f / ssum;
    #pragma unroll
    for (int k = 0; k < 9; k++) aff[k] = cand_v[k] ? aff[k] * rs : 0.f;

    if (PASS == 0) {
        // den: warp reduce each of 9 affinities over the 256 pixels
        __shared__ float denpart[8][9];
        #pragma unroll
        for (int k = 0; k < 9; k++) {
            float v = aff[k];
            v += __shfl_xor_sync(0xffffffffu, v, 16);
            v += __shfl_xor_sync(0xffffffffu, v, 8);
            v += __shfl_xor_sync(0xffffffffu, v, 4);
            v += __shfl_xor_sync(0xffffffffu, v, 2);
            v += __shfl_xor_sync(0xffffffffu, v, 1);
            if ((tid & 31) == 0) denpart[tid >> 5][k] = v;
        }
        __shared__ float aff_sm[9][256];
        #pragma unroll
        for (int k = 0; k < 9; k++) aff_sm[k][tid] = aff[k];
        __syncthreads();

        // num[k][c] = sum_p aff[k][p] * feats[c][p]
        int c = tid >> 2, g = tid & 3;
        const float* fc = x + (((size_t)b * Cc + c) << 16);
        int base = ((bi * 16) << 8) + bj * 16;
        float acc[9];
        #pragma unroll
        for (int k = 0; k < 9; k++) acc[k] = 0.f;
        for (int i = g; i < 256; i += 4) {
            float f = fc[base + ((i >> 4) << 8) + (i & 15)];
            #pragma unroll
            for (int k = 0; k < 9; k++) acc[k] = fmaf(aff_sm[k][i], f, acc[k]);
        }
        __shared__ float part[9][256];
        #pragma unroll
        for (int k = 0; k < 9; k++) part[k][tid] = acc[k];
        __syncthreads();

        for (int i = tid; i < 9 * 64; i += 256) {
            int k = i >> 6, c2i = i & 63;
            if (cand_v[k]) {
                int o4 = c2i * 4;
                float v = part[k][o4] + part[k][o4 + 1] + part[k][o4 + 2] + part[k][o4 + 3];
                atomicAdd(&g_num[(b * NS + cand_s[k]) * Cc + c2i], v);
            }
        }
        if (tid < 9 && cand_v[tid]) {
            float v = 0.f;
            #pragma unroll
            for (int w = 0; w < 8; w++) v += denpart[w][tid];
            atomicAdd(&g_den[b * NS + cand_s[tid]], v);
        }
    } else {
        // compact store: g_aff[b][k][p] = aff[k]   (coalesced per k-plane)
        float* ab = g_aff + (((size_t)b * 9) << 16) + p;
        #pragma unroll
        for (int k = 0; k < 9; k++)
            ab[(size_t)k << 16] = aff[k];
    }
}

// ---------------------------------------------------------------------------
// Writer: stream the full (B,nS,P) output, each byte written exactly once.
// CTA = one (b,s) plane (256KB). Nonzero iff pixel's block is in 3x3 of s;
// compact aff reads hit L2 (9.4MB).
// ---------------------------------------------------------------------------
__global__ __launch_bounds__(256) void write_out_kernel(float4* __restrict__ A) {
    int b = blockIdx.y, s = blockIdx.x;
    int si = s >> 4, sj = s & 15;
    float4* plane = A + ((size_t)(b * NS + s) << 14);          // 16384 float4
    const float* affb = g_aff + (((size_t)b * 9) << 16);
    int t = threadIdx.x;
    const float4 z = make_float4(0.f, 0.f, 0.f, 0.f);
    #pragma unroll 8
    for (int i = 0; i < 64; i++) {
        int e4 = i * 256 + t;
        int p = e4 << 2;
        int bi = p >> 12;                 // row>>4 = (p>>8)>>4
        int bj = (p & 255) >> 4;          // col block (4 cols per float4, same block)
        int di = si - bi + 1, dj = sj - bj + 1;
        float4 v = z;
        if ((unsigned)di <= 2u && (unsigned)dj <= 2u) {
            int k = di * 3 + dj;
            v = *(const float4*)(affb + ((size_t)k << 16) + p);
        }
        plane[e4] = v;
    }
}

extern "C" void kernel_launch(void* const* d_in, const int* in_sizes, int n_in,
                              void* d_out, int out_size) {
    const float* x = (const float*)d_in[0];
    float* A = (float*)d_out;

    dim3 grid(NS, Bn);
    // 1) initial centroids (cold DRAM read of x; x now L2-resident) + zero scratch
    init_cent_kernel<<<grid, 256>>>(x);
    // 2) pass 0: affinities + fused centroid-update reduction (x from L2)
    affinity_kernel<0><<<grid, 256>>>(x);
    // 3) pass 1: affinities with fused centroid finalize -> compact g_aff
    affinity_kernel<1><<<grid, 256>>>(x);
    // 4) stream the dense 256MB output once
    write_out_kernel<<<grid, 256>>>((float4*)A);
}

// round 3
// speedup vs baseline: 1.1819x; 1.1819x over previous
#include <cuda_runtime.h>

// Fixed shapes: x = (4,64,256,256) f32, stoken = 16
#define Bn 4
#define Cc 64
#define NH 16      // superpixel grid 16x16
#define NS 256     // nH*nW
#define PP 65536   // H*W

typedef unsigned long long ull;

// Scratch (allocation-free: __device__ globals)
__device__ float g_cent[Bn * NS * Cc];
__device__ float g_num [Bn * NS * Cc];
__device__ float g_den [Bn * NS];

__device__ __forceinline__ void ffma2(ull& acc, ull a, ull b) {
    asm("fma.rn.f32x2 %0, %1, %2, %0;" : "+l"(acc) : "l"(a), "l"(b));
}
__device__ __forceinline__ ull pack2(float x, float y) {
    ull r; asm("mov.b64 %0, {%1, %2};" : "=l"(r) : "f"(x), "f"(y)); return r;
}
__device__ __forceinline__ float2 unpack2(ull v) {
    float2 r; asm("mov.b64 {%0, %1}, %2;" : "=f"(r.x), "=f"(r.y) : "l"(v)); return r;
}

// ---------------------------------------------------------------------------
// Zero-fill: stream the output, SKIPPING float4s inside the 3x3 affinity
// region (those are written by pass 1 — disjoint 64B chunks, no ordering).
// ---------------------------------------------------------------------------
__global__ __launch_bounds__(256) void zero_fill_kernel(float4* __restrict__ A) {
    int b = blockIdx.y, s = blockIdx.x;
    int si = s >> 4, sj = s & 15;
    float4* plane = A + ((size_t)(b * NS + s) << 14);   // 16384 float4 per plane
    int t = threadIdx.x;
    const float4 z = make_float4(0.f, 0.f, 0.f, 0.f);
    #pragma unroll 8
    for (int i = 0; i < 64; i++) {
        int e4 = i * 256 + t;
        int p = e4 << 2;
        int bi = p >> 12;
        int bj = (p >> 4) & 15;
        int di = si - bi + 1, dj = sj - bj + 1;
        if ((unsigned)di > 2u || (unsigned)dj > 2u)
            __stcs(&plane[e4], z);
    }
}

// ---------------------------------------------------------------------------
// Initial centroids: block mean over each 16x16 block. Also zeroes scratch.
// ---------------------------------------------------------------------------
__global__ __launch_bounds__(256) void init_cent_kernel(const float* __restrict__ x) {
    int b = blockIdx.y, s = blockIdx.x;
    int bi = s >> 4, bj = s & 15;
    int tid = threadIdx.x;
    int c = tid >> 2, q = tid & 3;
    int base = ((bi * 16) << 8) + bj * 16;
    const float4* fc = (const float4*)(x + (((size_t)b * Cc + c) << 16) + base);
    float4 s4 = make_float4(0.f, 0.f, 0.f, 0.f);
    #pragma unroll 4
    for (int t = 0; t < 16; t++) {
        int j = q + t * 4;                 // float4 index within block
        float4 v = fc[(j >> 2) * 64 + (j & 3)];
        s4.x += v.x; s4.y += v.y; s4.z += v.z; s4.w += v.w;
    }
    float acc = (s4.x + s4.y) + (s4.z + s4.w);
    __shared__ float part[256];
    part[tid] = acc;
    __syncthreads();
    if (tid < 64) {
        int o4 = tid * 4;
        float v = (part[o4] + part[o4 + 1]) + (part[o4 + 2] + part[o4 + 3]);
        int idx = (b * NS + s) * Cc + tid;
        g_cent[idx] = v * (1.f / 256.f);
        g_num[idx]  = 0.f;
    }
    if (tid == 64) g_den[b * NS + s] = 0.f;
}

// ---------------------------------------------------------------------------
// Affinity pass. One CTA per (b, 16x16 pixel block); 256 threads = 256 pixels.
// PASS 0: centroids from g_cent; fused num/den reduction with global atomics.
// PASS 1: centroids from g_num/g_den (fused finalize); scatters into A.
// ---------------------------------------------------------------------------
template <int PASS>
__global__ __launch_bounds__(256) void affinity_kernel(const float* __restrict__ x,
                                                       float* __restrict__ A) {
    int b = blockIdx.y, sblk = blockIdx.x;
    int bi = sblk >> 4, bj = sblk & 15;
    int tid = threadIdx.x;

    __shared__ __align__(16) float cent_sm[9][64];
    __shared__ __align__(8)  float aff_sm[9][256];
    __shared__ float c2_sm[9];
    __shared__ float den_sm[9];
    __shared__ int   cand_s[9];
    __shared__ int   cand_v[9];

    if (tid < 9) {
        int ci = bi + tid / 3 - 1, cj = bj + tid % 3 - 1;
        int v = (ci >= 0 && ci < NH && cj >= 0 && cj < NH);
        cand_v[tid] = v;
        int s = v ? ci * NH + cj : 0;
        cand_s[tid] = s;
        if (PASS == 1) den_sm[tid] = g_den[b * NS + s] + 1e-16f;
    }
    __syncthreads();
    for (int i = tid; i < 9 * 64; i += 256) {
        int k = i >> 6, c = i & 63;
        int gi = (b * NS + cand_s[k]) * Cc + c;
        cent_sm[k][c] = (PASS == 0) ? g_cent[gi] : g_num[gi] / den_sm[k];
    }
    __syncthreads();
    if (tid < 9) {
        float s2 = 0.f;
        #pragma unroll 8
        for (int c = 0; c < 64; c++) { float v = cent_sm[tid][c]; s2 += v * v; }
        c2_sm[tid] = s2;
    }
    __syncthreads();

    // ---- per-pixel dots: 9 candidates x 64 channels, packed f32x2 FMA ----
    int ly = tid >> 4, lx = tid & 15;
    int p = ((bi * 16 + ly) << 8) + bj * 16 + lx;
    const float* fb = x + (((size_t)b * Cc) << 16) + p;
    ull dacc[9];
    #pragma unroll
    for (int k = 0; k < 9; k++) dacc[k] = 0ull;
    ull facc = 0ull;
    #pragma unroll 4
    for (int c = 0; c < 64; c += 4) {
        float f0 = fb[(size_t)(c + 0) << 16];
        float f1 = fb[(size_t)(c + 1) << 16];
        float f2v = fb[(size_t)(c + 2) << 16];
        float f3 = fb[(size_t)(c + 3) << 16];
        ull fp0 = pack2(f0, f1), fp1 = pack2(f2v, f3);
        ffma2(facc, fp0, fp0);
        ffma2(facc, fp1, fp1);
        #pragma unroll
        for (int k = 0; k < 9; k++) {
            float4 cv = *(const float4*)&cent_sm[k][c];
            ffma2(dacc[k], fp0, pack2(cv.x, cv.y));
            ffma2(dacc[k], fp1, pack2(cv.z, cv.w));
        }
    }
    float2 fh = unpack2(facc);
    float f2 = fh.x + fh.y;

    // ---- masked softmax over 9 candidates ----
    float aff[9];
    float mx = -3.0e38f;
    #pragma unroll
    for (int k = 0; k < 9; k++) {
        float2 dh = unpack2(dacc[k]);
        float d = f2 + c2_sm[k] - 2.f * (dh.x + dh.y);
        aff[k] = cand_v[k] ? -d : -1e30f;
        mx = fmaxf(mx, aff[k]);
    }
    float ssum = 0.f;
    #pragma unroll
    for (int k = 0; k < 9; k++) { float e = __expf(aff[k] - mx); aff[k] = e; ssum += e; }
    float rs = 1.f / ssum;
    #pragma unroll
    for (int k = 0; k < 9; k++) aff[k] = cand_v[k] ? aff[k] * rs : 0.f;

    #pragma unroll
    for (int k = 0; k < 9; k++) aff_sm[k][tid] = aff[k];

    if (PASS == 0) {
        // den: warp reduce each of 9 affinities over the 256 pixels
        __shared__ float denpart[8][9];
        #pragma unroll
        for (int k = 0; k < 9; k++) {
            float v = aff[k];
            v += __shfl_xor_sync(0xffffffffu, v, 16);
            v += __shfl_xor_sync(0xffffffffu, v, 8);
            v += __shfl_xor_sync(0xffffffffu, v, 4);
            v += __shfl_xor_sync(0xffffffffu, v, 2);
            v += __shfl_xor_sync(0xffffffffu, v, 1);
            if ((tid & 31) == 0) denpart[tid >> 5][k] = v;
        }
        __syncthreads();

        // num[k][c] = sum_p aff[k][p] * feats[c][p]  (pixel-pair f32x2)
        int c = tid >> 2, g = tid & 3;
        const float* fc = x + (((size_t)b * Cc + c) << 16);
        int base = ((bi * 16) << 8) + bj * 16;
        ull acc2[9];
        #pragma unroll
        for (int k = 0; k < 9; k++) acc2[k] = 0ull;
        #pragma unroll 4
        for (int q = 0; q < 32; q++) {
            int i = q * 8 + g * 2;                     // pixel pair (i, i+1)
            int row = i >> 4, col = i & 15;
            ull fp = *(const ull*)(fc + base + (row << 8) + col);
            #pragma unroll
            for (int k = 0; k < 9; k++)
                ffma2(acc2[k], fp, *(const ull*)&aff_sm[k][i]);
        }
        __shared__ float part[9][256];
        #pragma unroll
        for (int k = 0; k < 9; k++) {
            float2 h = unpack2(acc2[k]);
            part[k][tid] = h.x + h.y;
        }
        __syncthreads();

        for (int i = tid; i < 9 * 64; i += 256) {
            int k = i >> 6, c2i = i & 63;
            if (cand_v[k]) {
                int o4 = c2i * 4;
                float v = (part[k][o4] + part[k][o4 + 1]) + (part[k][o4 + 2] + part[k][o4 + 3]);
                atomicAdd(&g_num[(b * NS + cand_s[k]) * Cc + c2i], v);
            }
        }
        if (tid < 9 && cand_v[tid]) {
            float v = 0.f;
            #pragma unroll
            for (int w = 0; w < 8; w++) v += denpart[w][tid];
            atomicAdd(&g_den[b * NS + cand_s[tid]], v);
        }
    } else {
        // scatter into dense A with vectorized streaming stores
        __syncthreads();
        for (int i = tid; i < 9 * 64; i += 256) {
            int k = i >> 6, e4 = i & 63;
            if (cand_v[k]) {
                int row = e4 >> 2, c4 = e4 & 3;
                float4 v = *(const float4*)&aff_sm[k][row * 16 + c4 * 4];
                size_t off = (((size_t)(b * NS + cand_s[k])) << 16)
                           + (((bi * 16 + row) << 8) + bj * 16 + c4 * 4);
                __stcs((float4*)(A + off), v);
            }
        }
    }
}

extern "C" void kernel_launch(void* const* d_in, const int* in_sizes, int n_in,
                              void* d_out, int out_size) {
    const float* x = (const float*)d_in[0];
    float* A = (float*)d_out;

    static cudaStream_t s2 = nullptr;
    static cudaEvent_t ev0 = nullptr, ev1 = nullptr;
    if (!s2) {   // first call = correctness run (not captured): safe to create
        cudaStreamCreateWithFlags(&s2, cudaStreamNonBlocking);
        cudaEventCreateWithFlags(&ev0, cudaEventDisableTiming);
        cudaEventCreateWithFlags(&ev1, cudaEventDisableTiming);
    }

    dim3 grid(NS, Bn);

    // Fork: zero-fill runs concurrently with the compute chain.
    cudaEventRecord(ev0, 0);
    cudaStreamWaitEvent(s2, ev0, 0);
    zero_fill_kernel<<<grid, 256, 0, s2>>>((float4*)A);
    cudaEventRecord(ev1, s2);

    // Compute chain on the capture stream.
    init_cent_kernel<<<grid, 256>>>(x);
    affinity_kernel<0><<<grid, 256>>>(x, A);
    affinity_kernel<1><<<grid, 256>>>(x, A);

    // Join (required for valid capture; no data ordering needed — disjoint bytes).
    cudaStreamWaitEvent(0, ev1, 0);
}